// round 16
// baseline (speedup 1.0000x reference)
#include <cuda_runtime.h>
#include <cuda_fp16.h>
#include <cstdint>

#define NN   100000
#define NE   1600000
#define DIN  128
#define DH   128
#define DOUT 64
#define NBLK 98          // ceil(NN/1024)

// -------- scratch (device globals: allocation-guard safe) --------
__device__ __align__(16) __half g_feath[(size_t)NN * DIN];  // fp16 feat (gather payload)
__device__ __align__(16) __half g_g2h[(size_t)NN * DOUT];   // h1 @ W2, fp16
__device__ int    g_cnt[NN];      // in-degree; ZERO at entry (restored by scan_final)
__device__ int    g_rs[NN + 1];
__device__ int    g_cur[NN];
__device__ int    g_eord[NE];
__device__ int    g_bsum[NBLK];

// -------- tf32 mma helpers --------
__device__ __forceinline__ float tf32r(float f) {
    unsigned r; asm("cvt.rna.tf32.f32 %0, %1;" : "=r"(r) : "f"(f));
    return __uint_as_float(r);
}
__device__ __forceinline__ void mma_tf32(float* d, const unsigned* a,
                                         const unsigned* b) {
    asm("mma.sync.aligned.m16n8k8.row.col.f32.tf32.tf32.f32 "
        "{%0,%1,%2,%3}, {%4,%5,%6,%7}, {%8,%9}, {%0,%1,%2,%3};"
        : "+f"(d[0]), "+f"(d[1]), "+f"(d[2]), "+f"(d[3])
        : "r"(a[0]), "r"(a[1]), "r"(a[2]), "r"(a[3]), "r"(b[0]), "r"(b[1]));
}

// =================== cvt: feat -> fp16 (runs on side stream) ===================
__global__ void cvt_feat_kernel(const float* __restrict__ feat) {
    int stride = gridDim.x * blockDim.x;
    const float4* f4 = (const float4*)feat;
    uint2* o = (uint2*)g_feath;
    const int total = NN * DIN / 4;
    for (int i = blockIdx.x * blockDim.x + threadIdx.x; i < total; i += stride) {
        float4 v = f4[i];
        __half2 h0 = __floats2half2_rn(v.x, v.y);
        __half2 h1 = __floats2half2_rn(v.z, v.w);
        uint2 u;
        u.x = *(unsigned int*)&h0;
        u.y = *(unsigned int*)&h1;
        o[i] = u;
    }
}

// =================== hist: degree histogram ===================
__global__ void hist_kernel(const int* __restrict__ dst) {
    int stride = gridDim.x * blockDim.x;
    for (int i = blockIdx.x * blockDim.x + threadIdx.x; i < NE; i += stride)
        atomicAdd(&g_cnt[dst[i]], 1);   // no return -> RED
}

// =================== scan: blocksums, then final with inline lookback ==========
__global__ void scan_blocksums_kernel() {
    __shared__ int ws[32];
    int t = threadIdx.x, b = blockIdx.x;
    int i = b * 1024 + t;
    int v = (i < NN) ? g_cnt[i] : 0;
    int lane = t & 31, w = t >> 5;
    int x = v;
#pragma unroll
    for (int o = 16; o > 0; o >>= 1) x += __shfl_down_sync(~0u, x, o);
    if (lane == 0) ws[w] = x;
    __syncthreads();
    if (w == 0) {
        int y = ws[lane];
#pragma unroll
        for (int o = 16; o > 0; o >>= 1) y += __shfl_down_sync(~0u, y, o);
        if (lane == 0) g_bsum[b] = y;
    }
}

__global__ void scan_final_kernel() {
    __shared__ int ws[32];
    __shared__ int carry_s;
    int t = threadIdx.x, b = blockIdx.x;
    int lane = t & 31, w = t >> 5;

    // inline lookback: warp 1 sums preceding block sums (<=98 ints, L2-hot)
    if (w == 1) {
        int sum = 0;
        for (int j = lane; j < b; j += 32) sum += g_bsum[j];
#pragma unroll
        for (int o = 16; o > 0; o >>= 1) sum += __shfl_down_sync(~0u, sum, o);
        if (lane == 0) carry_s = sum;
    }

    int i = b * 1024 + t;
    int v = (i < NN) ? g_cnt[i] : 0;
    int x = v;
#pragma unroll
    for (int o = 1; o < 32; o <<= 1) {
        int y = __shfl_up_sync(~0u, x, o);
        if (lane >= o) x += y;
    }
    if (lane == 31) ws[w] = x;
    __syncthreads();
    if (w == 0) {
        int y = ws[lane];
#pragma unroll
        for (int o = 1; o < 32; o <<= 1) {
            int z = __shfl_up_sync(~0u, y, o);
            if (lane >= o) y += z;
        }
        ws[lane] = y;
    }
    __syncthreads();
    int incl = x + (w > 0 ? ws[w - 1] : 0);
    int excl = incl - v + carry_s;
    if (i < NN) { g_rs[i] = excl; g_cur[i] = excl; g_cnt[i] = 0; }
    if (b == 0 && t == 0) g_rs[NN] = NE;
}

__global__ void permute_kernel(const int* __restrict__ src,
                               const int* __restrict__ dst) {
    int stride = gridDim.x * blockDim.x;
    for (int e = blockIdx.x * blockDim.x + threadIdx.x; e < NE; e += stride) {
        int d = dst[e];
        int p = atomicAdd(&g_cur[d], 1);
        g_eord[p] = src[e];
    }
}

// =================== fused gather + tf32 tensor-core GEMM ===================
// Per block: 8 warps gather 8 nodes each (layer-1 aggregate, fp16 HADD2 pairs,
// fp32 accumulate, normalize, tf32 round) straight into the As smem tile;
// then h1 = relu(As@W1 + b1), g2h = fp16(h1@W2).
#define W1S_OFF 0
#define W2S_OFF (128 * 136)
#define B1S_OFF (W2S_OFF + 128 * 72)
#define AS_OFF  (B1S_OFF + 128)
#define SMEM_FLOATS (AS_OFF + 64 * 132)

__global__ __launch_bounds__(256, 1)
void gemm_fused_kernel(const float* __restrict__ W1,
                       const float* __restrict__ b1,
                       const float* __restrict__ W2) {
    extern __shared__ float sm[];
    float* W1s = sm + W1S_OFF;
    float* W2s = sm + W2S_OFF;
    float* b1s = sm + B1S_OFF;
    float* As  = sm + AS_OFF;
    const int tid = threadIdx.x;
    const int m0 = blockIdx.x * 64;
    const int wid = tid >> 5, lane = tid & 31;

    {   // stage W1 (tf32-rounded), stride 136
        const float4* w4 = (const float4*)W1;
        float4* s4 = (float4*)W1s;
#pragma unroll
        for (int it = 0; it < 16; it++) {
            int idx = tid + 256 * it;
            int k = idx >> 5, q = idx & 31;
            float4 v = w4[idx];
            v.x = tf32r(v.x); v.y = tf32r(v.y); v.z = tf32r(v.z); v.w = tf32r(v.w);
            s4[k * 34 + q] = v;
        }
        const float4* v4 = (const float4*)W2;
        float4* t4 = (float4*)W2s;
#pragma unroll
        for (int it = 0; it < 8; it++) {
            int idx = tid + 256 * it;
            int k = idx >> 4, q = idx & 15;
            float4 v = v4[idx];
            v.x = tf32r(v.x); v.y = tf32r(v.y); v.z = tf32r(v.z); v.w = tf32r(v.w);
            t4[k * 18 + q] = v;
        }
        if (tid < 128) b1s[tid] = b1[tid];
    }

    // ---- gather phase: warp wid handles nodes m0+wid*8 .. +7 ----
    {
        const int half = lane >> 4;
        const unsigned subb = (unsigned)(lane & 15) << 4;  // byte offset in row
        const char* fb = (const char*)g_feath;             // 256B per row
#pragma unroll 1
        for (int i = 0; i < 8; i++) {
            int row = wid * 8 + i;
            int n = m0 + row;
            float acc[8];
#pragma unroll
            for (int j = 0; j < 8; j++) acc[j] = 0.f;

            int beg = 0, end = 0;
            if (n < NN) { beg = g_rs[n]; end = g_rs[n + 1]; }

            if (n < NN && half == 0) {   // self term, counted once
                uint4 u = __ldg((const uint4*)(fb + (((unsigned)n << 8) + subb)));
                float2 f0 = __half22float2(*(__half2*)&u.x);
                float2 f1 = __half22float2(*(__half2*)&u.y);
                float2 f2 = __half22float2(*(__half2*)&u.z);
                float2 f3 = __half22float2(*(__half2*)&u.w);
                acc[0] = f0.x; acc[1] = f0.y; acc[2] = f1.x; acc[3] = f1.y;
                acc[4] = f2.x; acc[5] = f2.y; acc[6] = f3.x; acc[7] = f3.y;
            }

            int e = beg;
            for (; e + 8 <= end; e += 8) {   // 8 edges per iteration (4 per half)
                unsigned s0 = (unsigned)__ldg(&g_eord[e + half]) << 8;
                unsigned s1 = (unsigned)__ldg(&g_eord[e + 2 + half]) << 8;
                unsigned s2 = (unsigned)__ldg(&g_eord[e + 4 + half]) << 8;
                unsigned s3 = (unsigned)__ldg(&g_eord[e + 6 + half]) << 8;
                uint4 u0 = __ldg((const uint4*)(fb + (s0 + subb)));
                uint4 u1 = __ldg((const uint4*)(fb + (s1 + subb)));
                uint4 u2 = __ldg((const uint4*)(fb + (s2 + subb)));
                uint4 u3 = __ldg((const uint4*)(fb + (s3 + subb)));
                __half2 p0 = __hadd2(*(__half2*)&u0.x, *(__half2*)&u1.x);
                __half2 p1 = __hadd2(*(__half2*)&u0.y, *(__half2*)&u1.y);
                __half2 p2 = __hadd2(*(__half2*)&u0.z, *(__half2*)&u1.z);
                __half2 p3 = __hadd2(*(__half2*)&u0.w, *(__half2*)&u1.w);
                __half2 q0 = __hadd2(*(__half2*)&u2.x, *(__half2*)&u3.x);
                __half2 q1 = __hadd2(*(__half2*)&u2.y, *(__half2*)&u3.y);
                __half2 q2 = __hadd2(*(__half2*)&u2.z, *(__half2*)&u3.z);
                __half2 q3 = __hadd2(*(__half2*)&u2.w, *(__half2*)&u3.w);
                float2 f;
                f = __half22float2(p0); acc[0] += f.x; acc[1] += f.y;
                f = __half22float2(p1); acc[2] += f.x; acc[3] += f.y;
                f = __half22float2(p2); acc[4] += f.x; acc[5] += f.y;
                f = __half22float2(p3); acc[6] += f.x; acc[7] += f.y;
                f = __half22float2(q0); acc[0] += f.x; acc[1] += f.y;
                f = __half22float2(q1); acc[2] += f.x; acc[3] += f.y;
                f = __half22float2(q2); acc[4] += f.x; acc[5] += f.y;
                f = __half22float2(q3); acc[6] += f.x; acc[7] += f.y;
            }
            for (; e < end; e += 2) {        // tail: up to 2 edges, predicated
                int ee = e + half;
                bool v = ee < end;
                unsigned s = v ? ((unsigned)__ldg(&g_eord[ee]) << 8) : 0u;
                uint4 u = __ldg((const uint4*)(fb + (s + subb)));
                if (v) {
                    float2 f0 = __half22float2(*(__half2*)&u.x);
                    float2 f1 = __half22float2(*(__half2*)&u.y);
                    float2 f2 = __half22float2(*(__half2*)&u.z);
                    float2 f3 = __half22float2(*(__half2*)&u.w);
                    acc[0] += f0.x; acc[1] += f0.y; acc[2] += f1.x; acc[3] += f1.y;
                    acc[4] += f2.x; acc[5] += f2.y; acc[6] += f3.x; acc[7] += f3.y;
                }
            }
#pragma unroll
            for (int j = 0; j < 8; j++) acc[j] += __shfl_xor_sync(~0u, acc[j], 16);

            if (half == 0) {   // normalize, tf32 round, write to As tile
                float inv = (n < NN) ? 1.0f / (float)(end - beg + 1) : 0.f;
                float* p = &As[row * 132 + (subb >> 1)];   // subb/16*8 floats
#pragma unroll
                for (int j = 0; j < 8; j++) p[j] = tf32r(acc[j] * inv);
            }
        }
    }
    __syncthreads();

    const int wm = wid & 1;
    const int wn = wid >> 1;
    const int g = lane >> 2, t = lane & 3;

    // ---- phase 1: h1 = a1 @ W1 ----
    float d1[2][4][4];
#pragma unroll
    for (int im = 0; im < 2; im++)
#pragma unroll
        for (int jn = 0; jn < 4; jn++)
#pragma unroll
            for (int x = 0; x < 4; x++) d1[im][jn][x] = 0.f;

#pragma unroll 4
    for (int ks = 0; ks < 16; ks++) {
        int k0 = ks * 8;
        unsigned a[2][4];
#pragma unroll
        for (int im = 0; im < 2; im++) {
            int r0 = wm * 32 + im * 16 + g;
            a[im][0] = __float_as_uint(As[r0 * 132 + k0 + t]);
            a[im][1] = __float_as_uint(As[(r0 + 8) * 132 + k0 + t]);
            a[im][2] = __float_as_uint(As[r0 * 132 + k0 + t + 4]);
            a[im][3] = __float_as_uint(As[(r0 + 8) * 132 + k0 + t + 4]);
        }
#pragma unroll
        for (int jn = 0; jn < 4; jn++) {
            int col = wn * 32 + jn * 8 + g;
            unsigned b[2];
            b[0] = __float_as_uint(W1s[(k0 + t) * 136 + col]);
            b[1] = __float_as_uint(W1s[(k0 + t + 4) * 136 + col]);
            mma_tf32(d1[0][jn], a[0], b);
            mma_tf32(d1[1][jn], a[1], b);
        }
    }
    __syncthreads();

    {   // bias + relu -> As holds h1
#pragma unroll
        for (int im = 0; im < 2; im++) {
            int row = wm * 32 + im * 16 + g;
#pragma unroll
            for (int jn = 0; jn < 4; jn++) {
                int col = wn * 32 + jn * 8 + 2 * t;
                As[row * 132 + col]           = fmaxf(d1[im][jn][0] + b1s[col], 0.f);
                As[row * 132 + col + 1]       = fmaxf(d1[im][jn][1] + b1s[col + 1], 0.f);
                As[(row + 8) * 132 + col]     = fmaxf(d1[im][jn][2] + b1s[col], 0.f);
                As[(row + 8) * 132 + col + 1] = fmaxf(d1[im][jn][3] + b1s[col + 1], 0.f);
            }
        }
    }
    __syncthreads();

    // ---- phase 2: g2 = h1 @ W2 ----
    float d2[2][2][4];
#pragma unroll
    for (int im = 0; im < 2; im++)
#pragma unroll
        for (int jn = 0; jn < 2; jn++)
#pragma unroll
            for (int x = 0; x < 4; x++) d2[im][jn][x] = 0.f;

#pragma unroll 4
    for (int ks = 0; ks < 16; ks++) {
        int k0 = ks * 8;
        unsigned a[2][4];
#pragma unroll
        for (int im = 0; im < 2; im++) {
            int r0 = wm * 32 + im * 16 + g;
            a[im][0] = __float_as_uint(As[r0 * 132 + k0 + t]);
            a[im][1] = __float_as_uint(As[(r0 + 8) * 132 + k0 + t]);
            a[im][2] = __float_as_uint(As[r0 * 132 + k0 + t + 4]);
            a[im][3] = __float_as_uint(As[(r0 + 8) * 132 + k0 + t + 4]);
        }
#pragma unroll
        for (int jn = 0; jn < 2; jn++) {
            int col = wn * 16 + jn * 8 + g;
            unsigned b[2];
            b[0] = __float_as_uint(W2s[(k0 + t) * 72 + col]);
            b[1] = __float_as_uint(W2s[(k0 + t + 4) * 72 + col]);
            mma_tf32(d2[0][jn], a[0], b);
            mma_tf32(d2[1][jn], a[1], b);
        }
    }

    {   // write g2 as fp16
#pragma unroll
        for (int im = 0; im < 2; im++) {
            int row = wm * 32 + im * 16 + g;
            int m_lo = m0 + row, m_hi = m_lo + 8;
#pragma unroll
            for (int jn = 0; jn < 2; jn++) {
                int col = wn * 16 + jn * 8 + 2 * t;
                if (m_lo < NN) {
                    __half2 h = __floats2half2_rn(d2[im][jn][0], d2[im][jn][1]);
                    *(unsigned int*)(g_g2h + (size_t)m_lo * DOUT + col) =
                        *(unsigned int*)&h;
                }
                if (m_hi < NN) {
                    __half2 h = __floats2half2_rn(d2[im][jn][2], d2[im][jn][3]);
                    *(unsigned int*)(g_g2h + (size_t)m_hi * DOUT + col) =
                        *(unsigned int*)&h;
                }
            }
        }
    }
}

// =================== layer 2 aggregate + epilogue ===================
// One warp per node; 8 lanes x 16B per 128B row; 16 edges per main iteration.
__global__ void spmm2_kernel(const float* __restrict__ b2,
                             float* __restrict__ out) {
    int w = (blockIdx.x * blockDim.x + threadIdx.x) >> 5;
    int lane = threadIdx.x & 31;
    if (w >= NN) return;
    int beg = g_rs[w], end = g_rs[w + 1];
    const int grp = lane >> 3;
    const unsigned subb = (unsigned)(lane & 7) << 4;   // byte offset in row
    const char* gb = (const char*)g_g2h;               // 128B per row

    float acc[8];
#pragma unroll
    for (int j = 0; j < 8; j++) acc[j] = 0.f;

    if (grp == 0) {   // self
        uint4 u = __ldg((const uint4*)(gb + (((unsigned)w << 7) + subb)));
        float2 f0 = __half22float2(*(__half2*)&u.x);
        float2 f1 = __half22float2(*(__half2*)&u.y);
        float2 f2 = __half22float2(*(__half2*)&u.z);
        float2 f3 = __half22float2(*(__half2*)&u.w);
        acc[0] = f0.x; acc[1] = f0.y; acc[2] = f1.x; acc[3] = f1.y;
        acc[4] = f2.x; acc[5] = f2.y; acc[6] = f3.x; acc[7] = f3.y;
    }

    int e = beg;
    for (; e + 16 <= end; e += 16) {   // 16 edges per iteration (4 per group)
        unsigned s0 = (unsigned)__ldg(&g_eord[e + grp]) << 7;
        unsigned s1 = (unsigned)__ldg(&g_eord[e + 4 + grp]) << 7;
        unsigned s2 = (unsigned)__ldg(&g_eord[e + 8 + grp]) << 7;
        unsigned s3 = (unsigned)__ldg(&g_eord[e + 12 + grp]) << 7;
        uint4 u0 = __ldg((const uint4*)(gb + (s0 + subb)));
        uint4 u1 = __ldg((const uint4*)(gb + (s1 + subb)));
        uint4 u2 = __ldg((const uint4*)(gb + (s2 + subb)));
        uint4 u3 = __ldg((const uint4*)(gb + (s3 + subb)));
        __half2 p0 = __hadd2(*(__half2*)&u0.x, *(__half2*)&u1.x);
        __half2 p1 = __hadd2(*(__half2*)&u0.y, *(__half2*)&u1.y);
        __half2 p2 = __hadd2(*(__half2*)&u0.z, *(__half2*)&u1.z);
        __half2 p3 = __hadd2(*(__half2*)&u0.w, *(__half2*)&u1.w);
        __half2 q0 = __hadd2(*(__half2*)&u2.x, *(__half2*)&u3.x);
        __half2 q1 = __hadd2(*(__half2*)&u2.y, *(__half2*)&u3.y);
        __half2 q2 = __hadd2(*(__half2*)&u2.z, *(__half2*)&u3.z);
        __half2 q3 = __hadd2(*(__half2*)&u2.w, *(__half2*)&u3.w);
        float2 f;
        f = __half22float2(p0); acc[0] += f.x; acc[1] += f.y;
        f = __half22float2(p1); acc[2] += f.x; acc[3] += f.y;
        f = __half22float2(p2); acc[4] += f.x; acc[5] += f.y;
        f = __half22float2(p3); acc[6] += f.x; acc[7] += f.y;
        f = __half22float2(q0); acc[0] += f.x; acc[1] += f.y;
        f = __half22float2(q1); acc[2] += f.x; acc[3] += f.y;
        f = __half22float2(q2); acc[4] += f.x; acc[5] += f.y;
        f = __half22float2(q3); acc[6] += f.x; acc[7] += f.y;
    }
    for (; e < end; e += 4) {          // tail: up to 4 edges, predicated
        int ee = e + grp;
        bool v = ee < end;
        unsigned s = v ? ((unsigned)__ldg(&g_eord[ee]) << 7) : 0u;
        uint4 u = __ldg((const uint4*)(gb + (s + subb)));
        if (v) {
            float2 f0 = __half22float2(*(__half2*)&u.x);
            float2 f1 = __half22float2(*(__half2*)&u.y);
            float2 f2 = __half22float2(*(__half2*)&u.z);
            float2 f3 = __half22float2(*(__half2*)&u.w);
            acc[0] += f0.x; acc[1] += f0.y; acc[2] += f1.x; acc[3] += f1.y;
            acc[4] += f2.x; acc[5] += f2.y; acc[6] += f3.x; acc[7] += f3.y;
        }
    }
#pragma unroll
    for (int j = 0; j < 8; j++) acc[j] += __shfl_xor_sync(~0u, acc[j], 16);
#pragma unroll
    for (int j = 0; j < 8; j++) acc[j] += __shfl_xor_sync(~0u, acc[j], 8);

    if (lane < 8) {
        float inv = 1.0f / (float)(end - beg + 1);
        const float4* b4 = (const float4*)b2;
        float4 bb0 = b4[(lane & 7) * 2], bb1 = b4[(lane & 7) * 2 + 1];
        float4 r0, r1;
        r0.x = acc[0] * inv + bb0.x; r0.y = acc[1] * inv + bb0.y;
        r0.z = acc[2] * inv + bb0.z; r0.w = acc[3] * inv + bb0.w;
        r1.x = acc[4] * inv + bb1.x; r1.y = acc[5] * inv + bb1.y;
        r1.z = acc[6] * inv + bb1.z; r1.w = acc[7] * inv + bb1.w;
        float4* o = (float4*)((char*)out + (((size_t)w << 8) + (subb << 1)));
        o[0] = r0; o[1] = r1;
    }
}

// =================== launch ===================
extern "C" void kernel_launch(void* const* d_in, const int* in_sizes, int n_in,
                              void* d_out, int out_size) {
    const float* feat = (const float*)d_in[0];
    const float* W1   = (const float*)d_in[1];
    const float* b1   = (const float*)d_in[2];
    const float* W2   = (const float*)d_in[3];
    const float* b2   = (const float*)d_in[4];
    const int*   src  = (const int*)d_in[5];
    const int*   dst  = (const int*)d_in[6];
    float* out = (float*)d_out;

    const int smem = SMEM_FLOATS * (int)sizeof(float);   // ~140.8 KB
    cudaFuncSetAttribute(gemm_fused_kernel,
                         cudaFuncAttributeMaxDynamicSharedMemorySize, smem);

    // side stream + fork/join events (host-side objects; capture-safe)
    cudaStream_t s1;
    cudaStreamCreateWithFlags(&s1, cudaStreamNonBlocking);
    cudaEvent_t evFork, evJoin;
    cudaEventCreateWithFlags(&evFork, cudaEventDisableTiming);
    cudaEventCreateWithFlags(&evJoin, cudaEventDisableTiming);

    // fork: cvt runs concurrently with the CSR-build chain
    cudaEventRecord(evFork, 0);
    cudaStreamWaitEvent(s1, evFork, 0);
    cvt_feat_kernel<<<1184, 256, 0, s1>>>(feat);
    cudaEventRecord(evJoin, s1);

    hist_kernel<<<1024, 256>>>(dst);                 // g_cnt zero at entry
    scan_blocksums_kernel<<<NBLK, 1024>>>();
    scan_final_kernel<<<NBLK, 1024>>>();             // inline lookback; re-zeroes g_cnt
    permute_kernel<<<1024, 256>>>(src, dst);

    // join: fused gather+GEMM needs both g_feath (s1) and the CSR (stream 0)
    cudaStreamWaitEvent(0, evJoin, 0);
    gemm_fused_kernel<<<(NN + 63) / 64, 256, smem>>>(W1, b1, W2);
    spmm2_kernel<<<NN / 8, 256>>>(b2, out);
}

// round 17
// speedup vs baseline: 1.6588x; 1.6588x over previous
#include <cuda_runtime.h>
#include <cuda_fp16.h>
#include <cstdint>

#define NN   100000
#define NE   1600000
#define DIN  128
#define DH   128
#define DOUT 64
#define NBLK 98          // ceil(NN/1024)

// -------- scratch (device globals: allocation-guard safe) --------
__device__ float  g_a1[(size_t)NN * DIN];                   // aggregated input, fp32
__device__ __align__(16) __half g_feath[(size_t)NN * DIN];  // fp16 feat (gather payload)
__device__ __align__(16) __half g_g2h[(size_t)NN * DOUT];   // h1 @ W2, fp16
__device__ int    g_cnt[NN];      // in-degree; ZERO at entry (restored by scan_final)
__device__ int    g_rs[NN + 1];
__device__ int    g_cur[NN];
__device__ int    g_eord[NE];
__device__ int    g_bsum[NBLK];

// -------- tf32 mma helpers --------
__device__ __forceinline__ float tf32r(float f) {
    unsigned r; asm("cvt.rna.tf32.f32 %0, %1;" : "=r"(r) : "f"(f));
    return __uint_as_float(r);
}
__device__ __forceinline__ void mma_tf32(float* d, const unsigned* a,
                                         const unsigned* b) {
    asm("mma.sync.aligned.m16n8k8.row.col.f32.tf32.tf32.f32 "
        "{%0,%1,%2,%3}, {%4,%5,%6,%7}, {%8,%9}, {%0,%1,%2,%3};"
        : "+f"(d[0]), "+f"(d[1]), "+f"(d[2]), "+f"(d[3])
        : "r"(a[0]), "r"(a[1]), "r"(a[2]), "r"(a[3]), "r"(b[0]), "r"(b[1]));
}

// =================== cvt: feat -> fp16 (runs on side stream) ===================
__global__ void cvt_feat_kernel(const float* __restrict__ feat) {
    int stride = gridDim.x * blockDim.x;
    const float4* f4 = (const float4*)feat;
    uint2* o = (uint2*)g_feath;
    const int total = NN * DIN / 4;
    for (int i = blockIdx.x * blockDim.x + threadIdx.x; i < total; i += stride) {
        float4 v = f4[i];
        __half2 h0 = __floats2half2_rn(v.x, v.y);
        __half2 h1 = __floats2half2_rn(v.z, v.w);
        uint2 u;
        u.x = *(unsigned int*)&h0;
        u.y = *(unsigned int*)&h1;
        o[i] = u;
    }
}

// =================== hist: degree histogram ===================
__global__ void hist_kernel(const int* __restrict__ dst) {
    int stride = gridDim.x * blockDim.x;
    for (int i = blockIdx.x * blockDim.x + threadIdx.x; i < NE; i += stride)
        atomicAdd(&g_cnt[dst[i]], 1);   // no return -> RED
}

// =================== scan: blocksums, then final with inline lookback ==========
__global__ void scan_blocksums_kernel() {
    __shared__ int ws[32];
    int t = threadIdx.x, b = blockIdx.x;
    int i = b * 1024 + t;
    int v = (i < NN) ? g_cnt[i] : 0;
    int lane = t & 31, w = t >> 5;
    int x = v;
#pragma unroll
    for (int o = 16; o > 0; o >>= 1) x += __shfl_down_sync(~0u, x, o);
    if (lane == 0) ws[w] = x;
    __syncthreads();
    if (w == 0) {
        int y = ws[lane];
#pragma unroll
        for (int o = 16; o > 0; o >>= 1) y += __shfl_down_sync(~0u, y, o);
        if (lane == 0) g_bsum[b] = y;
    }
}

__global__ void scan_final_kernel() {
    __shared__ int ws[32];
    __shared__ int carry_s;
    int t = threadIdx.x, b = blockIdx.x;
    int lane = t & 31, w = t >> 5;

    // inline lookback: warp 1 sums preceding block sums (<=98 ints, L2-hot)
    if (w == 1) {
        int sum = 0;
        for (int j = lane; j < b; j += 32) sum += g_bsum[j];
#pragma unroll
        for (int o = 16; o > 0; o >>= 1) sum += __shfl_down_sync(~0u, sum, o);
        if (lane == 0) carry_s = sum;
    }

    int i = b * 1024 + t;
    int v = (i < NN) ? g_cnt[i] : 0;
    int x = v;
#pragma unroll
    for (int o = 1; o < 32; o <<= 1) {
        int y = __shfl_up_sync(~0u, x, o);
        if (lane >= o) x += y;
    }
    if (lane == 31) ws[w] = x;
    __syncthreads();
    if (w == 0) {
        int y = ws[lane];
#pragma unroll
        for (int o = 1; o < 32; o <<= 1) {
            int z = __shfl_up_sync(~0u, y, o);
            if (lane >= o) y += z;
        }
        ws[lane] = y;
    }
    __syncthreads();
    int incl = x + (w > 0 ? ws[w - 1] : 0);
    int excl = incl - v + carry_s;
    if (i < NN) { g_rs[i] = excl; g_cur[i] = excl; g_cnt[i] = 0; }
    if (b == 0 && t == 0) g_rs[NN] = NE;
}

__global__ void permute_kernel(const int* __restrict__ src,
                               const int* __restrict__ dst) {
    int stride = gridDim.x * blockDim.x;
    for (int e = blockIdx.x * blockDim.x + threadIdx.x; e < NE; e += stride) {
        int d = dst[e];
        int p = atomicAdd(&g_cur[d], 1);
        g_eord[p] = src[e];
    }
}

// =================== layer 1 aggregate (standalone, high occupancy) =============
// One warp per node; 16 lanes x 16B per 256B row; 8 edges per main iteration.
// fp16 pairwise HADD2 on edge pairs, then fp32 accumulate.
__global__ void spmm1_kernel() {
    int w = (blockIdx.x * blockDim.x + threadIdx.x) >> 5;
    int lane = threadIdx.x & 31;
    if (w >= NN) return;
    int beg = g_rs[w], end = g_rs[w + 1];
    const int half = lane >> 4;
    const unsigned subb = (unsigned)(lane & 15) << 4;   // byte offset in row
    const char* fb = (const char*)g_feath;              // 256B per row

    float acc[8];
#pragma unroll
    for (int j = 0; j < 8; j++) acc[j] = 0.f;

    if (half == 0) {   // self term, counted once
        uint4 u = __ldg((const uint4*)(fb + (((unsigned)w << 8) + subb)));
        float2 f0 = __half22float2(*(__half2*)&u.x);
        float2 f1 = __half22float2(*(__half2*)&u.y);
        float2 f2 = __half22float2(*(__half2*)&u.z);
        float2 f3 = __half22float2(*(__half2*)&u.w);
        acc[0] = f0.x; acc[1] = f0.y; acc[2] = f1.x; acc[3] = f1.y;
        acc[4] = f2.x; acc[5] = f2.y; acc[6] = f3.x; acc[7] = f3.y;
    }

    int e = beg;
    for (; e + 8 <= end; e += 8) {     // 8 edges per iteration (4 per half)
        unsigned s0 = (unsigned)__ldg(&g_eord[e + half]) << 8;
        unsigned s1 = (unsigned)__ldg(&g_eord[e + 2 + half]) << 8;
        unsigned s2 = (unsigned)__ldg(&g_eord[e + 4 + half]) << 8;
        unsigned s3 = (unsigned)__ldg(&g_eord[e + 6 + half]) << 8;
        uint4 u0 = __ldg((const uint4*)(fb + (s0 + subb)));
        uint4 u1 = __ldg((const uint4*)(fb + (s1 + subb)));
        uint4 u2 = __ldg((const uint4*)(fb + (s2 + subb)));
        uint4 u3 = __ldg((const uint4*)(fb + (s3 + subb)));
        // pair-sum in fp16 (one rounding per pair), then fp32 accumulate
        __half2 p0 = __hadd2(*(__half2*)&u0.x, *(__half2*)&u1.x);
        __half2 p1 = __hadd2(*(__half2*)&u0.y, *(__half2*)&u1.y);
        __half2 p2 = __hadd2(*(__half2*)&u0.z, *(__half2*)&u1.z);
        __half2 p3 = __hadd2(*(__half2*)&u0.w, *(__half2*)&u1.w);
        __half2 q0 = __hadd2(*(__half2*)&u2.x, *(__half2*)&u3.x);
        __half2 q1 = __hadd2(*(__half2*)&u2.y, *(__half2*)&u3.y);
        __half2 q2 = __hadd2(*(__half2*)&u2.z, *(__half2*)&u3.z);
        __half2 q3 = __hadd2(*(__half2*)&u2.w, *(__half2*)&u3.w);
        float2 f;
        f = __half22float2(p0); acc[0] += f.x; acc[1] += f.y;
        f = __half22float2(p1); acc[2] += f.x; acc[3] += f.y;
        f = __half22float2(p2); acc[4] += f.x; acc[5] += f.y;
        f = __half22float2(p3); acc[6] += f.x; acc[7] += f.y;
        f = __half22float2(q0); acc[0] += f.x; acc[1] += f.y;
        f = __half22float2(q1); acc[2] += f.x; acc[3] += f.y;
        f = __half22float2(q2); acc[4] += f.x; acc[5] += f.y;
        f = __half22float2(q3); acc[6] += f.x; acc[7] += f.y;
    }
    for (; e < end; e += 2) {          // tail: up to 2 edges, predicated
        int ee = e + half;
        bool v = ee < end;
        unsigned s = v ? ((unsigned)__ldg(&g_eord[ee]) << 8) : 0u;
        uint4 u = __ldg((const uint4*)(fb + (s + subb)));
        if (v) {
            float2 f0 = __half22float2(*(__half2*)&u.x);
            float2 f1 = __half22float2(*(__half2*)&u.y);
            float2 f2 = __half22float2(*(__half2*)&u.z);
            float2 f3 = __half22float2(*(__half2*)&u.w);
            acc[0] += f0.x; acc[1] += f0.y; acc[2] += f1.x; acc[3] += f1.y;
            acc[4] += f2.x; acc[5] += f2.y; acc[6] += f3.x; acc[7] += f3.y;
        }
    }
#pragma unroll
    for (int j = 0; j < 8; j++) acc[j] += __shfl_xor_sync(~0u, acc[j], 16);

    if (half == 0) {
        float inv = 1.0f / (float)(end - beg + 1);
        float4 r0 = make_float4(acc[0] * inv, acc[1] * inv, acc[2] * inv, acc[3] * inv);
        float4 r1 = make_float4(acc[4] * inv, acc[5] * inv, acc[6] * inv, acc[7] * inv);
        float4* o = (float4*)((char*)g_a1 + (((size_t)w << 9) + (subb << 1)));
        o[0] = r0; o[1] = r1;
    }
}

// =================== fused tf32 tensor-core GEMM ===================
// h1 = relu(a1@W1 + b1); g2h = fp16(h1@W2). 64-node tile, 256 threads (8 warps).
#define W1S_OFF 0
#define W2S_OFF (128 * 136)
#define B1S_OFF (W2S_OFF + 128 * 72)
#define AS_OFF  (B1S_OFF + 128)
#define SMEM_FLOATS (AS_OFF + 64 * 132)

__global__ __launch_bounds__(256, 1)
void gemm_fused_kernel(const float* __restrict__ W1,
                       const float* __restrict__ b1,
                       const float* __restrict__ W2) {
    extern __shared__ float sm[];
    float* W1s = sm + W1S_OFF;
    float* W2s = sm + W2S_OFF;
    float* b1s = sm + B1S_OFF;
    float* As  = sm + AS_OFF;
    const int tid = threadIdx.x;
    const int m0 = blockIdx.x * 64;

    {   // stage W1 (tf32-rounded), stride 136
        const float4* w4 = (const float4*)W1;
        float4* s4 = (float4*)W1s;
#pragma unroll
        for (int it = 0; it < 16; it++) {
            int idx = tid + 256 * it;
            int k = idx >> 5, q = idx & 31;
            float4 v = w4[idx];
            v.x = tf32r(v.x); v.y = tf32r(v.y); v.z = tf32r(v.z); v.w = tf32r(v.w);
            s4[k * 34 + q] = v;
        }
        const float4* v4 = (const float4*)W2;
        float4* t4 = (float4*)W2s;
#pragma unroll
        for (int it = 0; it < 8; it++) {
            int idx = tid + 256 * it;
            int k = idx >> 4, q = idx & 15;
            float4 v = v4[idx];
            v.x = tf32r(v.x); v.y = tf32r(v.y); v.z = tf32r(v.z); v.w = tf32r(v.w);
            t4[k * 18 + q] = v;
        }
        if (tid < 128) b1s[tid] = b1[tid];
        const float4* a4 = (const float4*)g_a1;
        float4* s = (float4*)As;
#pragma unroll
        for (int it = 0; it < 8; it++) {
            int idx = tid + 256 * it;
            int nr = idx >> 5, q = idx & 31;
            int m = m0 + nr;
            float4 v = make_float4(0.f, 0.f, 0.f, 0.f);
            if (m < NN) v = a4[(size_t)m * 32 + q];
            v.x = tf32r(v.x); v.y = tf32r(v.y); v.z = tf32r(v.z); v.w = tf32r(v.w);
            s[nr * 33 + q] = v;
        }
    }
    __syncthreads();

    const int wid = tid >> 5, lane = tid & 31;
    const int wm = wid & 1;
    const int wn = wid >> 1;
    const int g = lane >> 2, t = lane & 3;

    // ---- phase 1: h1 = a1 @ W1 ----
    float d1[2][4][4];
#pragma unroll
    for (int im = 0; im < 2; im++)
#pragma unroll
        for (int jn = 0; jn < 4; jn++)
#pragma unroll
            for (int x = 0; x < 4; x++) d1[im][jn][x] = 0.f;

#pragma unroll 4
    for (int ks = 0; ks < 16; ks++) {
        int k0 = ks * 8;
        unsigned a[2][4];
#pragma unroll
        for (int im = 0; im < 2; im++) {
            int r0 = wm * 32 + im * 16 + g;
            a[im][0] = __float_as_uint(As[r0 * 132 + k0 + t]);
            a[im][1] = __float_as_uint(As[(r0 + 8) * 132 + k0 + t]);
            a[im][2] = __float_as_uint(As[r0 * 132 + k0 + t + 4]);
            a[im][3] = __float_as_uint(As[(r0 + 8) * 132 + k0 + t + 4]);
        }
#pragma unroll
        for (int jn = 0; jn < 4; jn++) {
            int col = wn * 32 + jn * 8 + g;
            unsigned b[2];
            b[0] = __float_as_uint(W1s[(k0 + t) * 136 + col]);
            b[1] = __float_as_uint(W1s[(k0 + t + 4) * 136 + col]);
            mma_tf32(d1[0][jn], a[0], b);
            mma_tf32(d1[1][jn], a[1], b);
        }
    }
    __syncthreads();

    {   // bias + relu -> As holds h1
#pragma unroll
        for (int im = 0; im < 2; im++) {
            int row = wm * 32 + im * 16 + g;
#pragma unroll
            for (int jn = 0; jn < 4; jn++) {
                int col = wn * 32 + jn * 8 + 2 * t;
                As[row * 132 + col]           = fmaxf(d1[im][jn][0] + b1s[col], 0.f);
                As[row * 132 + col + 1]       = fmaxf(d1[im][jn][1] + b1s[col + 1], 0.f);
                As[(row + 8) * 132 + col]     = fmaxf(d1[im][jn][2] + b1s[col], 0.f);
                As[(row + 8) * 132 + col + 1] = fmaxf(d1[im][jn][3] + b1s[col + 1], 0.f);
            }
        }
    }
    __syncthreads();

    // ---- phase 2: g2 = h1 @ W2 ----
    float d2[2][2][4];
#pragma unroll
    for (int im = 0; im < 2; im++)
#pragma unroll
        for (int jn = 0; jn < 2; jn++)
#pragma unroll
            for (int x = 0; x < 4; x++) d2[im][jn][x] = 0.f;

#pragma unroll 4
    for (int ks = 0; ks < 16; ks++) {
        int k0 = ks * 8;
        unsigned a[2][4];
#pragma unroll
        for (int im = 0; im < 2; im++) {
            int r0 = wm * 32 + im * 16 + g;
            a[im][0] = __float_as_uint(As[r0 * 132 + k0 + t]);
            a[im][1] = __float_as_uint(As[(r0 + 8) * 132 + k0 + t]);
            a[im][2] = __float_as_uint(As[r0 * 132 + k0 + t + 4]);
            a[im][3] = __float_as_uint(As[(r0 + 8) * 132 + k0 + t + 4]);
        }
#pragma unroll
        for (int jn = 0; jn < 2; jn++) {
            int col = wn * 16 + jn * 8 + g;
            unsigned b[2];
            b[0] = __float_as_uint(W2s[(k0 + t) * 72 + col]);
            b[1] = __float_as_uint(W2s[(k0 + t + 4) * 72 + col]);
            mma_tf32(d2[0][jn], a[0], b);
            mma_tf32(d2[1][jn], a[1], b);
        }
    }

    {   // write g2 as fp16
#pragma unroll
        for (int im = 0; im < 2; im++) {
            int row = wm * 32 + im * 16 + g;
            int m_lo = m0 + row, m_hi = m_lo + 8;
#pragma unroll
            for (int jn = 0; jn < 2; jn++) {
                int col = wn * 16 + jn * 8 + 2 * t;
                if (m_lo < NN) {
                    __half2 h = __floats2half2_rn(d2[im][jn][0], d2[im][jn][1]);
                    *(unsigned int*)(g_g2h + (size_t)m_lo * DOUT + col) =
                        *(unsigned int*)&h;
                }
                if (m_hi < NN) {
                    __half2 h = __floats2half2_rn(d2[im][jn][2], d2[im][jn][3]);
                    *(unsigned int*)(g_g2h + (size_t)m_hi * DOUT + col) =
                        *(unsigned int*)&h;
                }
            }
        }
    }
}

// =================== layer 2 aggregate + epilogue ===================
// One warp per node; 8 lanes x 16B per 128B row; 16 edges per main iteration.
__global__ void spmm2_kernel(const float* __restrict__ b2,
                             float* __restrict__ out) {
    int w = (blockIdx.x * blockDim.x + threadIdx.x) >> 5;
    int lane = threadIdx.x & 31;
    if (w >= NN) return;
    int beg = g_rs[w], end = g_rs[w + 1];
    const int grp = lane >> 3;
    const unsigned subb = (unsigned)(lane & 7) << 4;   // byte offset in row
    const char* gb = (const char*)g_g2h;               // 128B per row

    float acc[8];
#pragma unroll
    for (int j = 0; j < 8; j++) acc[j] = 0.f;

    if (grp == 0) {   // self
        uint4 u = __ldg((const uint4*)(gb + (((unsigned)w << 7) + subb)));
        float2 f0 = __half22float2(*(__half2*)&u.x);
        float2 f1 = __half22float2(*(__half2*)&u.y);
        float2 f2 = __half22float2(*(__half2*)&u.z);
        float2 f3 = __half22float2(*(__half2*)&u.w);
        acc[0] = f0.x; acc[1] = f0.y; acc[2] = f1.x; acc[3] = f1.y;
        acc[4] = f2.x; acc[5] = f2.y; acc[6] = f3.x; acc[7] = f3.y;
    }

    int e = beg;
    for (; e + 16 <= end; e += 16) {   // 16 edges per iteration (4 per group)
        unsigned s0 = (unsigned)__ldg(&g_eord[e + grp]) << 7;
        unsigned s1 = (unsigned)__ldg(&g_eord[e + 4 + grp]) << 7;
        unsigned s2 = (unsigned)__ldg(&g_eord[e + 8 + grp]) << 7;
        unsigned s3 = (unsigned)__ldg(&g_eord[e + 12 + grp]) << 7;
        uint4 u0 = __ldg((const uint4*)(gb + (s0 + subb)));
        uint4 u1 = __ldg((const uint4*)(gb + (s1 + subb)));
        uint4 u2 = __ldg((const uint4*)(gb + (s2 + subb)));
        uint4 u3 = __ldg((const uint4*)(gb + (s3 + subb)));
        __half2 p0 = __hadd2(*(__half2*)&u0.x, *(__half2*)&u1.x);
        __half2 p1 = __hadd2(*(__half2*)&u0.y, *(__half2*)&u1.y);
        __half2 p2 = __hadd2(*(__half2*)&u0.z, *(__half2*)&u1.z);
        __half2 p3 = __hadd2(*(__half2*)&u0.w, *(__half2*)&u1.w);
        __half2 q0 = __hadd2(*(__half2*)&u2.x, *(__half2*)&u3.x);
        __half2 q1 = __hadd2(*(__half2*)&u2.y, *(__half2*)&u3.y);
        __half2 q2 = __hadd2(*(__half2*)&u2.z, *(__half2*)&u3.z);
        __half2 q3 = __hadd2(*(__half2*)&u2.w, *(__half2*)&u3.w);
        float2 f;
        f = __half22float2(p0); acc[0] += f.x; acc[1] += f.y;
        f = __half22float2(p1); acc[2] += f.x; acc[3] += f.y;
        f = __half22float2(p2); acc[4] += f.x; acc[5] += f.y;
        f = __half22float2(p3); acc[6] += f.x; acc[7] += f.y;
        f = __half22float2(q0); acc[0] += f.x; acc[1] += f.y;
        f = __half22float2(q1); acc[2] += f.x; acc[3] += f.y;
        f = __half22float2(q2); acc[4] += f.x; acc[5] += f.y;
        f = __half22float2(q3); acc[6] += f.x; acc[7] += f.y;
    }
    for (; e < end; e += 4) {          // tail: up to 4 edges, predicated
        int ee = e + grp;
        bool v = ee < end;
        unsigned s = v ? ((unsigned)__ldg(&g_eord[ee]) << 7) : 0u;
        uint4 u = __ldg((const uint4*)(gb + (s + subb)));
        if (v) {
            float2 f0 = __half22float2(*(__half2*)&u.x);
            float2 f1 = __half22float2(*(__half2*)&u.y);
            float2 f2 = __half22float2(*(__half2*)&u.z);
            float2 f3 = __half22float2(*(__half2*)&u.w);
            acc[0] += f0.x; acc[1] += f0.y; acc[2] += f1.x; acc[3] += f1.y;
            acc[4] += f2.x; acc[5] += f2.y; acc[6] += f3.x; acc[7] += f3.y;
        }
    }
#pragma unroll
    for (int j = 0; j < 8; j++) acc[j] += __shfl_xor_sync(~0u, acc[j], 16);
#pragma unroll
    for (int j = 0; j < 8; j++) acc[j] += __shfl_xor_sync(~0u, acc[j], 8);

    if (lane < 8) {
        float inv = 1.0f / (float)(end - beg + 1);
        const float4* b4 = (const float4*)b2;
        float4 bb0 = b4[(lane & 7) * 2], bb1 = b4[(lane & 7) * 2 + 1];
        float4 r0, r1;
        r0.x = acc[0] * inv + bb0.x; r0.y = acc[1] * inv + bb0.y;
        r0.z = acc[2] * inv + bb0.z; r0.w = acc[3] * inv + bb0.w;
        r1.x = acc[4] * inv + bb1.x; r1.y = acc[5] * inv + bb1.y;
        r1.z = acc[6] * inv + bb1.z; r1.w = acc[7] * inv + bb1.w;
        float4* o = (float4*)((char*)out + (((size_t)w << 8) + (subb << 1)));
        o[0] = r0; o[1] = r1;
    }
}

// =================== launch ===================
extern "C" void kernel_launch(void* const* d_in, const int* in_sizes, int n_in,
                              void* d_out, int out_size) {
    const float* feat = (const float*)d_in[0];
    const float* W1   = (const float*)d_in[1];
    const float* b1   = (const float*)d_in[2];
    const float* W2   = (const float*)d_in[3];
    const float* b2   = (const float*)d_in[4];
    const int*   src  = (const int*)d_in[5];
    const int*   dst  = (const int*)d_in[6];
    float* out = (float*)d_out;

    const int smem = SMEM_FLOATS * (int)sizeof(float);   // ~140.8 KB
    cudaFuncSetAttribute(gemm_fused_kernel,
                         cudaFuncAttributeMaxDynamicSharedMemorySize, smem);

    // side stream + fork/join events (host-side objects; capture-safe)
    cudaStream_t s1;
    cudaStreamCreateWithFlags(&s1, cudaStreamNonBlocking);
    cudaEvent_t evFork, evJoin;
    cudaEventCreateWithFlags(&evFork, cudaEventDisableTiming);
    cudaEventCreateWithFlags(&evJoin, cudaEventDisableTiming);

    // fork: cvt runs concurrently with the CSR-build chain
    cudaEventRecord(evFork, 0);
    cudaStreamWaitEvent(s1, evFork, 0);
    cvt_feat_kernel<<<1184, 256, 0, s1>>>(feat);
    cudaEventRecord(evJoin, s1);

    hist_kernel<<<1024, 256>>>(dst);                 // g_cnt zero at entry
    scan_blocksums_kernel<<<NBLK, 1024>>>();
    scan_final_kernel<<<NBLK, 1024>>>();             // inline lookback; re-zeroes g_cnt
    permute_kernel<<<1024, 256>>>(src, dst);

    // join: spmm1 needs both g_feath (s1) and the CSR (stream 0)
    cudaStreamWaitEvent(0, evJoin, 0);
    spmm1_kernel<<<NN / 8, 256>>>();
    gemm_fused_kernel<<<(NN + 63) / 64, 256, smem>>>(W1, b1, W2);
    spmm2_kernel<<<NN / 8, 256>>>(b2, out);
}